// round 16
// baseline (speedup 1.0000x reference)
#include <cuda_runtime.h>
#include <cuda_fp16.h>
#include <math.h>
#include <stdint.h>

#define B_  2
#define S_  2048
#define D_  1024
#define H_  16
#define DK_ 64
#define M_  (B_*S_)

// ---------------------------------------------------------------------------
// Scratch (__device__ globals; allocation-free contract)
// ---------------------------------------------------------------------------
__device__ __align__(16) __half g_Xh [M_*D_];            // X fp16
__device__ __align__(16) __half g_Wh [4*(size_t)D_*D_];  // weights fp16 [mat][n][k]
__device__ __align__(16) __half g_AOh[M_*D_];            // attn out fp16 [B,S,D]
__device__ __align__(16) __half g_Q[B_*H_*S_*DK_];       // [B,H,S,DK], *log2(e)/8
__device__ __align__(16) __half g_K[B_*H_*S_*DK_];       // [B,H,S,DK]
__device__ __align__(16) __half g_V[B_*H_*S_*DK_];       // [B,H,DK,S] (transposed)

// ---------------------------------------------------------------------------
// PTX wrappers
// ---------------------------------------------------------------------------
__device__ __forceinline__ uint32_t smem_u32(const void* p) {
    uint32_t a;
    asm("{ .reg .u64 t; cvta.to.shared.u64 t, %1; cvt.u32.u64 %0, t; }"
        : "=r"(a) : "l"(p));
    return a;
}
__device__ __forceinline__ void cp16(uint32_t dst, const void* src) {
    asm volatile("cp.async.cg.shared.global [%0], [%1], 16;"
                 :: "r"(dst), "l"(src));
}
#define CP_COMMIT() asm volatile("cp.async.commit_group;")
#define CP_WAIT1()  asm volatile("cp.async.wait_group 1;")

__device__ __forceinline__ void ldm4(uint32_t (&a)[4], uint32_t addr) {
    asm volatile("ldmatrix.sync.aligned.m8n8.x4.shared.b16 {%0,%1,%2,%3}, [%4];"
                 : "=r"(a[0]), "=r"(a[1]), "=r"(a[2]), "=r"(a[3]) : "r"(addr));
}
__device__ __forceinline__ void mma_f16(float (&d)[4], const uint32_t (&a)[4],
                                        uint32_t b0, uint32_t b1) {
    asm volatile(
        "mma.sync.aligned.m16n8k16.row.col.f32.f16.f16.f32 "
        "{%0,%1,%2,%3}, {%4,%5,%6,%7}, {%8,%9}, {%0,%1,%2,%3};"
        : "+f"(d[0]), "+f"(d[1]), "+f"(d[2]), "+f"(d[3])
        : "r"(a[0]), "r"(a[1]), "r"(a[2]), "r"(a[3]), "r"(b0), "r"(b1));
}
__device__ __forceinline__ float ex2f(float x) {
    float y; asm("ex2.approx.f32 %0, %1;" : "=f"(y) : "f"(x)); return y;
}
__device__ __forceinline__ uint32_t packh2(float a, float b) {
    uint32_t r;
    asm("cvt.rn.f16x2.f32 %0, %1, %2;" : "=r"(r) : "f"(b), "f"(a));
    return r;
}

#define SC_Q 0.18033688011112042f   // log2(e)/8, folded into Q at projection

// ---------------------------------------------------------------------------
// Prep (single launch): blocks [0,2048) convert X, [2048,4096) convert W.
// ---------------------------------------------------------------------------
__device__ __forceinline__ void conv8h(const float* src, __half* dst, size_t i) {
    float4 v = *(const float4*)(src + i);
    float4 w = *(const float4*)(src + i + 4);
    uint4 r;
    r.x = packh2(v.x, v.y);
    r.y = packh2(v.z, v.w);
    r.z = packh2(w.x, w.y);
    r.w = packh2(w.z, w.w);
    *(uint4*)(dst + i) = r;
}
__global__ __launch_bounds__(256)
void conv_all(const float* __restrict__ x,
              const float* __restrict__ w0, const float* __restrict__ w1,
              const float* __restrict__ w2, const float* __restrict__ w3,
              __half* __restrict__ Xh, __half* __restrict__ Wh)
{
    const int bx = blockIdx.x;
    if (bx < 2048) {
        size_t i = ((size_t)bx * 256 + threadIdx.x) * 8;
        conv8h(x, Xh, i);
    } else {
        size_t j = ((size_t)(bx - 2048) * 256 + threadIdx.x) * 8;
        const int m = (int)(j >> 20);
        const float* srcs[4] = {w0, w1, w2, w3};
        conv8h(srcs[m], Wh + ((size_t)m << 20), j & 1048575u);
    }
}

// ---------------------------------------------------------------------------
// fp16 GEMM (R15 version, verified): CTA 128x128, 16 warps of 32x32, BK=64,
// 3-stage, 2 CTA/SM.
// DEST 0: Cout fp32 [M,D];  DEST 1: fused QKV epilogue (N=3072 grid).
// ---------------------------------------------------------------------------
#define BM 128
#define BN 128
#define BK 64
#define NIT (D_/BK)
#define HROWB 144
#define TSB_OFFB (BM*HROWB)
#define TSTG ((BM+BN)*HROWB)
#define NSTG 3
#define TSMEM (NSTG*TSTG)
#define GTHR 512

template<int DEST>
__global__ __launch_bounds__(GTHR, 2)
void gemm_f16(const __half* __restrict__ A, const __half* __restrict__ W,
              float* __restrict__ Cout, const int* __restrict__ tokpos)
{
    extern __shared__ __align__(16) char smem[];
    const int tid  = threadIdx.x;
    const int lane = tid & 31, w = tid >> 5;
    const int wm = (w & 3) * 32;
    const int wn = (w >> 2) * 32;
    const int m0 = blockIdx.x * BM;
    const int n0 = blockIdx.y * BN;

    auto load_stage = [&](int st, int it) {
        char* s = smem + st * TSTG;
        const int kk = it * BK;
#pragma unroll
        for (int i = 0; i < 2; i++) {
            int idx = tid + i * GTHR;
            int row = idx >> 3, ch = idx & 7;
            cp16(smem_u32(s + row * HROWB + ch * 16),
                 A + (size_t)(m0 + row) * D_ + kk + ch * 8);
        }
        char* sB = s + TSB_OFFB;
#pragma unroll
        for (int i = 0; i < 2; i++) {
            int idx = tid + i * GTHR;
            int row = idx >> 3, ch = idx & 7;
            cp16(smem_u32(sB + row * HROWB + ch * 16),
                 W + (size_t)(n0 + row) * D_ + kk + ch * 8);
        }
    };

    float acc[2][4][4];
#pragma unroll
    for (int mt = 0; mt < 2; mt++)
#pragma unroll
        for (int nt = 0; nt < 4; nt++)
#pragma unroll
            for (int r = 0; r < 4; r++) acc[mt][nt][r] = 0.f;

    load_stage(0, 0); CP_COMMIT();
    load_stage(1, 1); CP_COMMIT();

    const uint32_t sbase = smem_u32(smem);
    const int ri = lane & 7, mi = lane >> 3;
    const uint32_t a_lm = (uint32_t)((wm + (lane & 15)) * HROWB + ((lane >> 4) << 4));
    const uint32_t b_lm = (uint32_t)(TSB_OFFB + (wn + ri + 8 * (mi >> 1)) * HROWB
                                     + (mi & 1) * 16);

    for (int it = 0; it < NIT; it++) {
        CP_WAIT1();
        __syncthreads();
        if (it + 2 < NIT) load_stage((it + 2) % NSTG, it + 2);
        CP_COMMIT();

        const uint32_t st = sbase + (uint32_t)((it % NSTG) * TSTG);
#pragma unroll
        for (int ks = 0; ks < 4; ks++) {
            uint32_t a0[4], a1[4];
            ldm4(a0, st + a_lm + ks * 32);
            ldm4(a1, st + a_lm + 16 * HROWB + ks * 32);
#pragma unroll
            for (int j = 0; j < 2; j++) {
                uint32_t bb[4];
                ldm4(bb, st + b_lm + j * 16 * HROWB + ks * 32);
                mma_f16(acc[0][2 * j],     a0, bb[0], bb[1]);
                mma_f16(acc[1][2 * j],     a1, bb[0], bb[1]);
                mma_f16(acc[0][2 * j + 1], a0, bb[2], bb[3]);
                mma_f16(acc[1][2 * j + 1], a1, bb[2], bb[3]);
            }
        }
    }

#pragma unroll
    for (int mt = 0; mt < 2; mt++) {
        const int r0 = m0 + wm + mt * 16 + (lane >> 2);
#pragma unroll
        for (int nt = 0; nt < 4; nt++) {
            const int ncol = n0 + wn + nt * 8 + (lane & 3) * 2;
            if (DEST == 0) {
                *(float2*)(Cout + (size_t)r0 * D_ + ncol) =
                    make_float2(acc[mt][nt][0], acc[mt][nt][1]);
                *(float2*)(Cout + (size_t)(r0 + 8) * D_ + ncol) =
                    make_float2(acc[mt][nt][2], acc[mt][nt][3]);
            } else {
                const int mat = ncol >> 10;          // 0=Q, 1=K, 2=V
                const int c   = ncol & 1023;
                const int h = c >> 6, dk = c & 63;
                if (mat == 2) {
#pragma unroll
                    for (int rr = 0; rr < 2; rr++) {
                        const int m = r0 + rr * 8;
                        const int bb = m >> 11, ss = m & (S_ - 1);
                        size_t base = ((size_t)(bb * H_ + h)) * DK_ * S_;
                        g_V[base + (size_t)dk * S_ + ss] =
                            __float2half_rn(acc[mt][nt][2 * rr]);
                        g_V[base + (size_t)(dk + 1) * S_ + ss] =
                            __float2half_rn(acc[mt][nt][2 * rr + 1]);
                    }
                } else {
                    __half* Dst = (mat == 0) ? g_Q : g_K;
                    const float fr = powf(10000.f, -(float)dk / 64.f);
#pragma unroll
                    for (int rr = 0; rr < 2; rr++) {
                        const int m = r0 + rr * 8;
                        const int bb = m >> 11, ss = m & (S_ - 1);
                        const float pos = (float)tokpos[ss];
                        float sn, cs;
                        sincosf(pos * fr, &sn, &cs);
                        float e  = acc[mt][nt][2 * rr];
                        float od = acc[mt][nt][2 * rr + 1];
                        float v0 = e * cs - od * sn;
                        float v1 = e * sn + od * cs;
                        if (mat == 0) { v0 *= SC_Q; v1 *= SC_Q; }
                        size_t ib = (((size_t)(bb * H_ + h)) * S_ + ss) * DK_ + dk;
                        *(uint32_t*)(Dst + ib) = packh2(v0, v1);
                    }
                }
            }
        }
    }
}

// ---------------------------------------------------------------------------
// Flash attention, fp16 k16. CTA = 128q x 64kv, 8 warps of 16q, 2 CTA/SM.
// Per-warp code path identical to the verified 64q kernel (bit-exact);
// KV loads amortized over 2x the q rows. P register-resident.
// ---------------------------------------------------------------------------
#define ATHR 256
#define AROWB 144
#define AQ_B (128*AROWB)                     // 18432 B (Q region, 128 rows)
#define AKV_B (2*64*AROWB)                   // 18432 B per stage (K+V)
#define ATT_SMEM (AQ_B + 2*AKV_B)            // 55296 -> 2 CTA/SM... (227KB/55KB=4) -> 4 CTA/SM if regs allow

__global__ __launch_bounds__(ATHR)
void attn_f16()
{
    extern __shared__ __align__(16) char sm[];
    const int tid = threadIdx.x;
    const int lane = tid & 31, w = tid >> 5;   // 8 warps, warp w owns q rows [16w,16w+16)
    const int qt = (int)(gridDim.x - 1 - blockIdx.x);  // long rows first
    const int h  = blockIdx.y, b = blockIdx.z;
    const int q0 = qt * 128;
    const int ktmax = 2 * qt + 1;
    const size_t gqk = ((size_t)(b * H_ + h)) * S_ * DK_;
    const size_t gvt = ((size_t)(b * H_ + h)) * DK_ * S_;

    // Q tile: 128 rows x 8 chunks(16B)
#pragma unroll
    for (int i = 0; i < 4; i++) {
        int idx = tid + i * ATHR;
        int r = idx >> 3, ch = idx & 7;
        cp16(smem_u32(sm + r * AROWB + ch * 16),
             g_Q + gqk + (size_t)(q0 + r) * DK_ + ch * 8);
    }
    auto load_kv = [&](int st, int kt) {
        char* sK = sm + AQ_B + st * AKV_B;
        char* sV = sK + 64 * AROWB;
#pragma unroll
        for (int i = 0; i < 2; i++) {
            int idx = tid + i * ATHR;
            int r = idx >> 3, ch = idx & 7;
            cp16(smem_u32(sK + r * AROWB + ch * 16),
                 g_K + gqk + (size_t)(kt * 64 + r) * DK_ + ch * 8);
            cp16(smem_u32(sV + r * AROWB + ch * 16),
                 g_V + gvt + (size_t)r * S_ + kt * 64 + ch * 8);
        }
    };
    load_kv(0, 0); CP_COMMIT();
    load_kv(1, 1); CP_COMMIT();   // ktmax >= 1 always

    CP_WAIT1();
    __syncthreads();

    const uint32_t sbase = smem_u32(sm);
    const int ri = lane & 7, mi = lane >> 3;
    const uint32_t q_lm = (uint32_t)((w * 16 + (lane & 15)) * AROWB + ((lane >> 4) << 4));
    const uint32_t kb_lm = (uint32_t)((ri + 8 * (mi >> 1)) * AROWB + (mi & 1) * 16);
    uint32_t qf[4][4];
#pragma unroll
    for (int ks = 0; ks < 4; ks++)
        ldm4(qf[ks], sbase + q_lm + ks * 32);

    float o[8][4];
#pragma unroll
    for (int d = 0; d < 8; d++)
#pragma unroll
        for (int r = 0; r < 4; r++) o[d][r] = 0.f;
    float mi0 = -1e30f, mi1 = -1e30f, li0 = 0.f, li1 = 0.f;
    const int row_lo = w * 16 + (lane >> 2);   // local q row (0..127)
    const int colx   = 2 * (lane & 3);

    for (int kt = 0; kt <= ktmax; kt++) {
        if (kt) { CP_WAIT1(); __syncthreads(); }
        const uint32_t sK = sbase + AQ_B + (kt & 1) * AKV_B;
        const uint32_t sV = sK + 64 * AROWB;

        // ---- S = Q K^T ----
        float s[8][4];
#pragma unroll
        for (int nt = 0; nt < 8; nt++)
#pragma unroll
            for (int r = 0; r < 4; r++) s[nt][r] = 0.f;
#pragma unroll
        for (int ks = 0; ks < 4; ks++)
#pragma unroll
            for (int j = 0; j < 4; j++) {
                uint32_t kb[4];
                ldm4(kb, sK + kb_lm + j * 16 * AROWB + ks * 32);
                mma_f16(s[2 * j],     qf[ks], kb[0], kb[1]);
                mma_f16(s[2 * j + 1], qf[ks], kb[2], kb[3]);
            }

        // ---- causal mask (tiles at/after the diagonal band) ----
        if (kt >= 2 * qt) {
            const int dq = (kt - 2 * qt) * 64;   // k0 - q0
#pragma unroll
            for (int nt = 0; nt < 8; nt++) {
                const int c = nt * 8 + colx + dq;
                if (c     > row_lo)     s[nt][0] = -1e30f;
                if (c + 1 > row_lo)     s[nt][1] = -1e30f;
                if (c     > row_lo + 8) s[nt][2] = -1e30f;
                if (c + 1 > row_lo + 8) s[nt][3] = -1e30f;
            }
        }

        // ---- online softmax (base-2; scale folded into Q) ----
        float r0 = -1e30f, r1 = -1e30f;
#pragma unroll
        for (int nt = 0; nt < 8; nt++) {
            r0 = fmaxf(r0, fmaxf(s[nt][0], s[nt][1]));
            r1 = fmaxf(r1, fmaxf(s[nt][2], s[nt][3]));
        }
        r0 = fmaxf(r0, __shfl_xor_sync(0xffffffffu, r0, 1));
        r0 = fmaxf(r0, __shfl_xor_sync(0xffffffffu, r0, 2));
        r1 = fmaxf(r1, __shfl_xor_sync(0xffffffffu, r1, 1));
        r1 = fmaxf(r1, __shfl_xor_sync(0xffffffffu, r1, 2));
        const float mn0 = fmaxf(mi0, r0), mn1 = fmaxf(mi1, r1);
        const float c0 = ex2f(mi0 - mn0), c1 = ex2f(mi1 - mn1);
        float sum0 = 0.f, sum1 = 0.f;
#pragma unroll
        for (int nt = 0; nt < 8; nt++) {
            s[nt][0] = ex2f(s[nt][0] - mn0);
            s[nt][1] = ex2f(s[nt][1] - mn0);
            s[nt][2] = ex2f(s[nt][2] - mn1);
            s[nt][3] = ex2f(s[nt][3] - mn1);
            sum0 += s[nt][0] + s[nt][1];
            sum1 += s[nt][2] + s[nt][3];
        }
        sum0 += __shfl_xor_sync(0xffffffffu, sum0, 1);
        sum0 += __shfl_xor_sync(0xffffffffu, sum0, 2);
        sum1 += __shfl_xor_sync(0xffffffffu, sum1, 1);
        sum1 += __shfl_xor_sync(0xffffffffu, sum1, 2);
        li0 = li0 * c0 + sum0; li1 = li1 * c1 + sum1;
        mi0 = mn0; mi1 = mn1;
#pragma unroll
        for (int d = 0; d < 8; d++) {
            o[d][0] *= c0; o[d][1] *= c0; o[d][2] *= c1; o[d][3] *= c1;
        }

        // ---- O += P V : P packed in registers ----
#pragma unroll
        for (int ks = 0; ks < 4; ks++) {
            uint32_t pa[4];
            pa[0] = packh2(s[2 * ks][0],     s[2 * ks][1]);
            pa[1] = packh2(s[2 * ks][2],     s[2 * ks][3]);
            pa[2] = packh2(s[2 * ks + 1][0], s[2 * ks + 1][1]);
            pa[3] = packh2(s[2 * ks + 1][2], s[2 * ks + 1][3]);
#pragma unroll
            for (int j = 0; j < 4; j++) {
                uint32_t vb[4];
                ldm4(vb, sV + kb_lm + j * 16 * AROWB + ks * 32);
                mma_f16(o[2 * j],     pa, vb[0], vb[1]);
                mma_f16(o[2 * j + 1], pa, vb[2], vb[3]);
            }
        }

        __syncthreads();
        if (kt + 2 <= ktmax) load_kv(kt & 1, kt + 2);
        CP_COMMIT();
    }

    // ---- epilogue: normalize, write fp16 [B,S,H*DK] ----
    const float inv0 = 1.f / li0, inv1 = 1.f / li1;
    const int grow0 = q0 + row_lo;
#pragma unroll
    for (int d = 0; d < 8; d++) {
        const int cb = h * 64 + d * 8 + colx;
        *(uint32_t*)(g_AOh + ((size_t)b * S_ + grow0) * D_ + cb) =
            packh2(o[d][0] * inv0, o[d][1] * inv0);
        *(uint32_t*)(g_AOh + ((size_t)b * S_ + grow0 + 8) * D_ + cb) =
            packh2(o[d][2] * inv1, o[d][3] * inv1);
    }
}

// ---------------------------------------------------------------------------
// Host
// ---------------------------------------------------------------------------
extern "C" void kernel_launch(void* const* d_in, const int* in_sizes, int n_in,
                              void* d_out, int out_size)
{
    const float* x  = (const float*)d_in[0];
    const float* qw = (const float*)d_in[1];
    const float* kw = (const float*)d_in[2];
    const float* vw = (const float*)d_in[3];
    const float* ow = (const float*)d_in[4];
    const int*   tp = (const int*)d_in[6];
    float* out = (float*)d_out;

    void *xh, *wh, *aoh;
    cudaGetSymbolAddress(&xh,  g_Xh);
    cudaGetSymbolAddress(&wh,  g_Wh);
    cudaGetSymbolAddress(&aoh, g_AOh);
    __half* Xh  = (__half*)xh;
    __half* Wh  = (__half*)wh;
    __half* AOh = (__half*)aoh;

    conv_all<<<4096, 256>>>(x, qw, kw, vw, ow, Xh, Wh);

    cudaFuncSetAttribute(gemm_f16<0>, cudaFuncAttributeMaxDynamicSharedMemorySize, TSMEM);
    cudaFuncSetAttribute(gemm_f16<1>, cudaFuncAttributeMaxDynamicSharedMemorySize, TSMEM);
    cudaFuncSetAttribute(attn_f16, cudaFuncAttributeMaxDynamicSharedMemorySize, ATT_SMEM);

    dim3 qkvgrid(M_ / BM, 3 * D_ / BN);   // (32, 24)
    gemm_f16<1><<<qkvgrid, GTHR, TSMEM>>>(Xh, Wh, nullptr, tp);

    dim3 agrid(S_ / 128, H_, B_);         // (16, 16, 2)
    attn_f16<<<agrid, ATHR, ATT_SMEM>>>();

    dim3 ogrid(M_ / BM, D_ / BN);         // (32, 8)
    gemm_f16<0><<<ogrid, GTHR, TSMEM>>>(AOh, Wh + 3*(size_t)D_*D_, out, tp);
}